// round 1
// baseline (speedup 1.0000x reference)
#include <cuda_runtime.h>

#define EMAX 800000
#define K1DIM 128   // 2H
#define C1 256      // 4H
#define C2 64       // H
#define EPSV 1e-5f

// -------- scratch (static device arrays; no runtime allocation) ----------
__device__ float g_Y1[(size_t)EMAX * C1];   // layer-1 pre-norm output
__device__ float g_Y2[(size_t)EMAX * C2];   // layer-2 pre-norm output
__device__ float g_s1[2 * C1];              // sum, sumsq for layer 1
__device__ float g_mr1[2 * C1];             // mean, rstd for layer 1
__device__ float g_s2[2 * C2];
__device__ float g_mr2[2 * C2];
__device__ int   g_idx64;                   // 1 if edge_index is int64

// -------- pre: zero stats + detect index dtype ---------------------------
__global__ void k_pre(const int* __restrict__ ei_words)
{
    int gid = blockIdx.x * blockDim.x + threadIdx.x;
    if (gid == 0) {
        // If edge_index is int64 (indices < 2^31), every odd 32-bit word is 0.
        // If int32, odd words are random values in [0, 50000): P(all zero) ~ 0.
        int orv = 0;
        #pragma unroll
        for (int i = 1; i < 32; i += 2) orv |= ei_words[i];
        g_idx64 = (orv == 0) ? 1 : 0;
    }
    if (gid < 2 * C1) g_s1[gid] = 0.0f;
    if (gid < 2 * C2) g_s2[gid] = 0.0f;
}

// -------- layer 1: gather-concat GEMM + channel stats --------------------
// Persistent CTAs. smem: W1 [128][256] (128KB) + A tile [32][128] (16KB).
// 256 threads: tx = tid&31 -> 8 cols, ty = tid>>5 -> 4 rows. 32 acc/thread.
__global__ __launch_bounds__(256, 1)
void k_gemm1(const float* __restrict__ emb,
             const void* __restrict__ ei,
             const float* __restrict__ W1,
             const float* __restrict__ b1,
             int E)
{
    extern __shared__ float sm[];
    float* Ws = sm;                 // 128*256
    float* As = sm + K1DIM * C1;    // 32*128

    const int tid = threadIdx.x;
    for (int i = tid; i < K1DIM * C1 / 4; i += blockDim.x)
        ((float4*)Ws)[i] = ((const float4*)W1)[i];

    const long long* ei64 = (const long long*)ei;
    const int*       ei32 = (const int*)ei;
    const int is64 = g_idx64;

    const int tx = tid & 31;   // col group: cols [tx*8, tx*8+8)
    const int ty = tid >> 5;   // row group: rows [ty*4, ty*4+4)

    float biasReg[8];
    #pragma unroll
    for (int c = 0; c < 8; c++) biasReg[c] = b1[tx * 8 + c];

    float rSum[8], rSq[8];
    #pragma unroll
    for (int c = 0; c < 8; c++) { rSum[c] = 0.0f; rSq[c] = 0.0f; }

    __syncthreads();

    const int nTiles = (E + 31) / 32;
    for (int tile = blockIdx.x; tile < nTiles; tile += gridDim.x) {
        const int base = tile * 32;

        // gather: 32 rows x 128 floats (= 32 float4 per row), coalesced
        for (int i = tid; i < 32 * 32; i += blockDim.x) {
            const int r = i >> 5, q = i & 31;
            const int e = base + r;
            float4 v = make_float4(0.f, 0.f, 0.f, 0.f);
            if (e < E) {
                long long src;
                if (q < 16) src = is64 ? ei64[e]     : (long long)ei32[e];
                else        src = is64 ? ei64[E + e] : (long long)ei32[E + e];
                v = *(const float4*)(emb + src * 64 + (q & 15) * 4);
            }
            ((float4*)(As + r * K1DIM))[q] = v;
        }
        __syncthreads();

        float acc[4][8];
        #pragma unroll
        for (int r = 0; r < 4; r++)
            #pragma unroll
            for (int c = 0; c < 8; c++) acc[r][c] = 0.0f;

        const float* Arow = As + (ty * 4) * K1DIM;
        #pragma unroll 4
        for (int k = 0; k < K1DIM; k++) {
            const float4 w0 = *((const float4*)(Ws + k * C1 + tx * 8));
            const float4 w1 = *((const float4*)(Ws + k * C1 + tx * 8 + 4));
            const float a0 = Arow[k];
            const float a1 = Arow[K1DIM + k];
            const float a2 = Arow[2 * K1DIM + k];
            const float a3 = Arow[3 * K1DIM + k];
            #define FMA8(r, a)                                            \
                acc[r][0] += (a) * w0.x; acc[r][1] += (a) * w0.y;         \
                acc[r][2] += (a) * w0.z; acc[r][3] += (a) * w0.w;         \
                acc[r][4] += (a) * w1.x; acc[r][5] += (a) * w1.y;         \
                acc[r][6] += (a) * w1.z; acc[r][7] += (a) * w1.w;
            FMA8(0, a0) FMA8(1, a1) FMA8(2, a2) FMA8(3, a3)
            #undef FMA8
        }

        #pragma unroll
        for (int r = 0; r < 4; r++) {
            const int e = base + ty * 4 + r;
            if (e < E) {
                float v[8];
                #pragma unroll
                for (int c = 0; c < 8; c++) {
                    v[c] = acc[r][c] + biasReg[c];
                    rSum[c] += v[c];
                    rSq[c]  += v[c] * v[c];
                }
                float4* dst = (float4*)(g_Y1 + (size_t)e * C1 + tx * 8);
                dst[0] = make_float4(v[0], v[1], v[2], v[3]);
                dst[1] = make_float4(v[4], v[5], v[6], v[7]);
            }
        }
        __syncthreads();
    }

    // block reduce per-channel partial sums (8 ty groups), then global atomics
    float* redS = sm;            // [8][256]
    float* redQ = sm + 8 * C1;   // [8][256]
    __syncthreads();
    #pragma unroll
    for (int c = 0; c < 8; c++) {
        redS[ty * C1 + tx * 8 + c] = rSum[c];
        redQ[ty * C1 + tx * 8 + c] = rSq[c];
    }
    __syncthreads();
    if (tid < C1) {
        float s = 0.f, q = 0.f;
        #pragma unroll
        for (int g = 0; g < 8; g++) { s += redS[g * C1 + tid]; q += redQ[g * C1 + tid]; }
        atomicAdd(&g_s1[tid], s);
        atomicAdd(&g_s1[C1 + tid], q);
    }
}

__global__ void k_fin1(float invE)
{
    const int c = threadIdx.x;
    if (c < C1) {
        const float m   = g_s1[c] * invE;
        const float var = g_s1[C1 + c] * invE - m * m;
        g_mr1[c]      = m;
        g_mr1[C1 + c] = rsqrtf(var + EPSV);
    }
}

// -------- layer 2: norm+relu(Y1) @ W2 + stats ----------------------------
// smem: W2 [256][64] (64KB) + A tile [64][260] (66.6KB) + mean/rstd (2KB).
// 256 threads: tx = tid&15 -> 4 cols, ty = tid>>4 -> 4 rows. 16 acc/thread.
#define A2S 260
__global__ __launch_bounds__(256, 1)
void k_gemm2(const float* __restrict__ W2,
             const float* __restrict__ b2,
             int E)
{
    extern __shared__ float sm[];
    float* Ws = sm;                       // 256*64
    float* As = Ws + C1 * C2;             // 64*260
    float* Ms = As + 64 * A2S;            // 256 means
    float* Rs = Ms + C1;                  // 256 rstds

    const int tid = threadIdx.x;
    for (int i = tid; i < C1 * C2 / 4; i += blockDim.x)
        ((float4*)Ws)[i] = ((const float4*)W2)[i];
    for (int i = tid; i < C1; i += blockDim.x) {
        Ms[i] = g_mr1[i];
        Rs[i] = g_mr1[C1 + i];
    }

    const int tx = tid & 15;   // cols [tx*4, tx*4+4)
    const int ty = tid >> 4;   // rows [ty*4, ty*4+4)

    float biasReg[4];
    #pragma unroll
    for (int c = 0; c < 4; c++) biasReg[c] = b2[tx * 4 + c];

    float rSum[4] = {0.f, 0.f, 0.f, 0.f};
    float rSq[4]  = {0.f, 0.f, 0.f, 0.f};

    __syncthreads();

    const int nTiles = (E + 63) / 64;
    for (int tile = blockIdx.x; tile < nTiles; tile += gridDim.x) {
        const int base = tile * 64;

        // load + normalize + relu Y1 tile: 64 rows x 64 float4
        for (int i = tid; i < 64 * 64; i += blockDim.x) {
            const int r = i >> 6, q = i & 63;
            const int e = base + r;
            float4 v = make_float4(0.f, 0.f, 0.f, 0.f);
            if (e < E) v = ((const float4*)(g_Y1 + (size_t)e * C1))[q];
            const int c0 = q * 4;
            v.x = fmaxf(0.f, (v.x - Ms[c0 + 0]) * Rs[c0 + 0]);
            v.y = fmaxf(0.f, (v.y - Ms[c0 + 1]) * Rs[c0 + 1]);
            v.z = fmaxf(0.f, (v.z - Ms[c0 + 2]) * Rs[c0 + 2]);
            v.w = fmaxf(0.f, (v.w - Ms[c0 + 3]) * Rs[c0 + 3]);
            ((float4*)(As + r * A2S))[q] = v;
        }
        __syncthreads();

        float acc[4][4];
        #pragma unroll
        for (int r = 0; r < 4; r++)
            #pragma unroll
            for (int c = 0; c < 4; c++) acc[r][c] = 0.0f;

        const float* Arow = As + (ty * 4) * A2S;
        #pragma unroll 4
        for (int k = 0; k < C1; k++) {
            const float4 w = *((const float4*)(Ws + k * C2 + tx * 4));
            const float a0 = Arow[k];
            const float a1 = Arow[A2S + k];
            const float a2 = Arow[2 * A2S + k];
            const float a3 = Arow[3 * A2S + k];
            acc[0][0] += a0 * w.x; acc[0][1] += a0 * w.y; acc[0][2] += a0 * w.z; acc[0][3] += a0 * w.w;
            acc[1][0] += a1 * w.x; acc[1][1] += a1 * w.y; acc[1][2] += a1 * w.z; acc[1][3] += a1 * w.w;
            acc[2][0] += a2 * w.x; acc[2][1] += a2 * w.y; acc[2][2] += a2 * w.z; acc[2][3] += a2 * w.w;
            acc[3][0] += a3 * w.x; acc[3][1] += a3 * w.y; acc[3][2] += a3 * w.z; acc[3][3] += a3 * w.w;
        }

        #pragma unroll
        for (int r = 0; r < 4; r++) {
            const int e = base + ty * 4 + r;
            if (e < E) {
                float v[4];
                #pragma unroll
                for (int c = 0; c < 4; c++) {
                    v[c] = acc[r][c] + biasReg[c];
                    rSum[c] += v[c];
                    rSq[c]  += v[c] * v[c];
                }
                *((float4*)(g_Y2 + (size_t)e * C2 + tx * 4)) =
                    make_float4(v[0], v[1], v[2], v[3]);
            }
        }
        __syncthreads();
    }

    // block reduce (16 ty groups x 64 cols), then global atomics
    float* redS = sm;             // [16][64]
    float* redQ = sm + 16 * C2;   // [16][64]
    __syncthreads();
    #pragma unroll
    for (int c = 0; c < 4; c++) {
        redS[ty * C2 + tx * 4 + c] = rSum[c];
        redQ[ty * C2 + tx * 4 + c] = rSq[c];
    }
    __syncthreads();
    if (tid < C2) {
        float s = 0.f, q = 0.f;
        #pragma unroll
        for (int g = 0; g < 16; g++) { s += redS[g * C2 + tid]; q += redQ[g * C2 + tid]; }
        atomicAdd(&g_s2[tid], s);
        atomicAdd(&g_s2[C2 + tid], q);
    }
}

__global__ void k_fin2(float invE)
{
    const int c = threadIdx.x;
    if (c < C2) {
        const float m   = g_s2[c] * invE;
        const float var = g_s2[C2 + c] * invE - m * m;
        g_mr2[c]      = m;
        g_mr2[C2 + c] = rsqrtf(var + EPSV);
    }
}

// -------- layer 3: norm+relu(Y2) @ W3 + b3 -------------------------------
// warp per edge row, float2 per lane, shuffle reduce.
__global__ void k_out(const float* __restrict__ W3,
                      const float* __restrict__ b3,
                      float* __restrict__ out,
                      int E)
{
    __shared__ float w[C2], m[C2], rs[C2];
    const int tid = threadIdx.x;
    if (tid < C2) {
        w[tid]  = W3[tid];
        m[tid]  = g_mr2[tid];
        rs[tid] = g_mr2[C2 + tid];
    }
    __syncthreads();

    const int lane = tid & 31;
    const int warp = tid >> 5;
    const int e = blockIdx.x * (blockDim.x >> 5) + warp;
    if (e >= E) return;

    const float2 y = ((const float2*)(g_Y2 + (size_t)e * C2))[lane];
    const int c = lane * 2;
    float p = fmaxf(0.f, (y.x - m[c])     * rs[c])     * w[c]
            + fmaxf(0.f, (y.y - m[c + 1]) * rs[c + 1]) * w[c + 1];
    #pragma unroll
    for (int o = 16; o > 0; o >>= 1) p += __shfl_down_sync(0xffffffffu, p, o);
    if (lane == 0) out[e] = p + b3[0];
}

// -------- launch ----------------------------------------------------------
extern "C" void kernel_launch(void* const* d_in, const int* in_sizes, int n_in,
                              void* d_out, int out_size)
{
    const float* emb = (const float*)d_in[0];
    const void*  ei  = d_in[1];
    const float* W1  = (const float*)d_in[2];
    const float* b1  = (const float*)d_in[3];
    const float* W2  = (const float*)d_in[4];
    const float* b2  = (const float*)d_in[5];
    const float* W3  = (const float*)d_in[6];
    const float* b3  = (const float*)d_in[7];
    float* out = (float*)d_out;

    const int E = in_sizes[1] / 2;

    int dev = 0;
    cudaGetDevice(&dev);
    int nsm = 148;
    cudaDeviceGetAttribute(&nsm, cudaDevAttrMultiProcessorCount, dev);

    const int sm1 = (K1DIM * C1 + 32 * K1DIM) * (int)sizeof(float);      // 147456
    const int sm2 = (C1 * C2 + 64 * A2S + 2 * C1) * (int)sizeof(float);  // 134144
    cudaFuncSetAttribute(k_gemm1, cudaFuncAttributeMaxDynamicSharedMemorySize, sm1);
    cudaFuncSetAttribute(k_gemm2, cudaFuncAttributeMaxDynamicSharedMemorySize, sm2);

    k_pre<<<2, 256>>>((const int*)ei);
    k_gemm1<<<nsm, 256, sm1>>>(emb, ei, W1, b1, E);
    k_fin1<<<1, 256>>>(1.0f / (float)E);
    k_gemm2<<<nsm, 256, sm2>>>(W2, b2, E);
    k_fin2<<<1, 64>>>(1.0f / (float)E);
    k_out<<<(E + 7) / 8, 256>>>(W3, b3, out, E);
}